// round 2
// baseline (speedup 1.0000x reference)
#include <cuda_runtime.h>
#include <math.h>

#define T_LEN 256
#define BB 64
#define SENT_D 320
#define UU 512
#define G4 2048
#define HD 1024

// ---------------- scratch (device globals; no allocs allowed) ----------------
__device__ float g_sent[T_LEN * BB * SENT_D];
__device__ float g_preF[(size_t)T_LEN * BB * G4];
__device__ float g_preB[(size_t)T_LEN * BB * G4];
__device__ float g_in2[(size_t)T_LEN * BB * 1024];   // [t][b][0:512]=fwd1, [512:1024]=back1
__device__ float g_fwd2[(size_t)T_LEN * BB * UU];
__device__ float g_back2[(size_t)T_LEN * BB * UU];

__device__ float g_Wx1f[SENT_D * G4], g_Wx1b[SENT_D * G4];
__device__ float g_Wh1f[UU * G4],     g_Wh1b[UU * G4];
__device__ float g_Wx2f[1024 * G4],   g_Wx2b[1024 * G4];
__device__ float g_Wh2f[UU * G4],     g_Wh2b[UU * G4];
__device__ float g_bv1f[G4], g_bv1b[G4], g_bv2f[G4], g_bv2b[G4];

__device__ float g_hFa[BB * UU], g_hFb[BB * UU];
__device__ float g_hBa[BB * UU], g_hBb[BB * UU];
__device__ float g_cF[BB * UU],  g_cB[BB * UU];

__device__ float g_hi_s[BB * 8192];
__device__ float g_hi_l[BB * 6144];
__device__ float g_part_s[16 * BB * HD];
__device__ float g_part_l[12 * BB * HD];
__device__ float g_hs[BB * HD], g_hl[BB * HD];

// ---------------- weight packing: column n = u*4 + k (gate-interleaved) ------
__global__ void pack_lstm(const float* __restrict__ W, const float* __restrict__ b,
                          float* __restrict__ Wx, float* __restrict__ Wh,
                          float* __restrict__ bv, int din) {
    int total = 4 * (din + UU) * UU;
    int stride = gridDim.x * blockDim.x;
    for (int idx = blockIdx.x * blockDim.x + threadIdx.x; idx < total; idx += stride) {
        int k = idx / ((din + UU) * UU);
        int rem = idx - k * ((din + UU) * UU);
        int d = rem / UU;
        int u = rem - d * UU;
        float v = W[idx];
        int n = u * 4 + k;
        if (d < din) Wx[(size_t)d * G4 + n] = v;
        else         Wh[(size_t)(d - din) * G4 + n] = v;
    }
    for (int i = blockIdx.x * blockDim.x + threadIdx.x; i < G4; i += stride) {
        int k = i & 3, u = i >> 2;
        bv[i] = b[k * UU + u];
    }
}

// ---------------- embedding gather + concat ----------------------------------
__global__ void embed_kernel(const float* __restrict__ we, const float* __restrict__ te,
                             const int* __restrict__ wi, const int* __restrict__ ti) {
    int idx = blockIdx.x * blockDim.x + threadIdx.x;   // grid sized exactly
    int tb = idx / SENT_D;
    int j = idx - tb * SENT_D;
    float v;
    if (j < 256) v = we[(size_t)wi[tb] * 256 + j];
    else         v = te[(size_t)ti[tb] * 64 + (j - 256)];
    g_sent[idx] = v;
}

// ---------------- LSTM state init --------------------------------------------
__global__ void init_states(const float* __restrict__ c0f, const float* __restrict__ c0b) {
    int idx = blockIdx.x * blockDim.x + threadIdx.x;   // B*U = 32768
    int u = idx & (UU - 1);
    float cf = c0f[u], cb = c0b[u];
    g_cF[idx] = cf;  g_hFa[idx] = tanhf(cf);
    g_cB[idx] = cb;  g_hBa[idx] = tanhf(cb);
}

// ---------------- big SGEMM: C = A@B, 128x128 tiles, fp32 --------------------
__global__ void __launch_bounds__(256) sgemm_128x128(
    const float* __restrict__ A, const float* __restrict__ B, float* __restrict__ C,
    int K, int lda, int ldb, int ldc) {
    __shared__ float As[16][132];   // As[kk][m]
    __shared__ float Bs[16][132];   // Bs[kk][n]
    int m0 = blockIdx.y * 128, n0 = blockIdx.x * 128;
    int tid = threadIdx.x;
    int tx = tid & 15, ty = tid >> 4;
    float acc[8][8];
#pragma unroll
    for (int i = 0; i < 8; i++)
#pragma unroll
        for (int j = 0; j < 8; j++) acc[i][j] = 0.f;

    int ar = tid >> 2, ac = (tid & 3) * 4;
    int bk = tid >> 5, bn = (tid & 31) * 4;

    for (int k0 = 0; k0 < K; k0 += 16) {
        float4 a0 = *(const float4*)(A + (size_t)(m0 + ar) * lda + k0 + ac);
        float4 a1 = *(const float4*)(A + (size_t)(m0 + ar + 64) * lda + k0 + ac);
        float4 b0 = *(const float4*)(B + (size_t)(k0 + bk) * ldb + n0 + bn);
        float4 b1 = *(const float4*)(B + (size_t)(k0 + bk + 8) * ldb + n0 + bn);
        __syncthreads();
        As[ac + 0][ar] = a0.x; As[ac + 1][ar] = a0.y; As[ac + 2][ar] = a0.z; As[ac + 3][ar] = a0.w;
        As[ac + 0][ar + 64] = a1.x; As[ac + 1][ar + 64] = a1.y; As[ac + 2][ar + 64] = a1.z; As[ac + 3][ar + 64] = a1.w;
        *(float4*)&Bs[bk][bn] = b0;
        *(float4*)&Bs[bk + 8][bn] = b1;
        __syncthreads();
#pragma unroll
        for (int kk = 0; kk < 16; kk++) {
            float4 av0 = *(float4*)&As[kk][ty * 8];
            float4 av1 = *(float4*)&As[kk][ty * 8 + 4];
            float4 bv0 = *(float4*)&Bs[kk][tx * 8];
            float4 bv1 = *(float4*)&Bs[kk][tx * 8 + 4];
            float a[8] = {av0.x, av0.y, av0.z, av0.w, av1.x, av1.y, av1.z, av1.w};
            float bb[8] = {bv0.x, bv0.y, bv0.z, bv0.w, bv1.x, bv1.y, bv1.z, bv1.w};
#pragma unroll
            for (int i = 0; i < 8; i++)
#pragma unroll
                for (int j = 0; j < 8; j++) acc[i][j] += a[i] * bb[j];
        }
    }
#pragma unroll
    for (int i = 0; i < 8; i++) {
        float4 v0 = {acc[i][0], acc[i][1], acc[i][2], acc[i][3]};
        float4 v1 = {acc[i][4], acc[i][5], acc[i][6], acc[i][7]};
        float* cp = C + (size_t)(m0 + ty * 8 + i) * ldc + n0 + tx * 8;
        *(float4*)cp = v0;
        *(float4*)(cp + 4) = v1;
    }
}

// ---------------- one recurrent step, both directions fused ------------------
// grid = 64 CTAs: blk>>5 = dir, blk&31 = 64-wide n-tile (16 complete units)
__global__ void __launch_bounds__(256) lstm_step(
    const float* __restrict__ preF, const float* __restrict__ preB,
    const float* __restrict__ WhF,  const float* __restrict__ WhB,
    const float* __restrict__ bvF,  const float* __restrict__ bvB,
    const float* __restrict__ hinF, float* __restrict__ houtF,
    const float* __restrict__ hinB, float* __restrict__ houtB,
    float* __restrict__ outF, float* __restrict__ outB,
    int ostride, int tF, int tB) {
    __shared__ float AsT[16][68];   // AsT[kk][b]
    __shared__ float Bs[16][68];    // Bs[kk][n]
    int blk = blockIdx.x;
    int dir = blk >> 5;
    int nb = blk & 31;
    int n0 = nb * 64;

    const float* pre = dir ? preB : preF;
    const float* Wh  = dir ? WhB : WhF;
    const float* bv  = dir ? bvB : bvF;
    const float* hin = dir ? hinB : hinF;
    float* hout = dir ? houtB : houtF;
    float* cst  = dir ? g_cB : g_cF;
    float* outp = dir ? outB : outF;
    int t = dir ? tB : tF;

    int tid = threadIdx.x;
    int tx = tid & 15, ty = tid >> 4;
    float acc[4][4] = {{0}};

    int ab = tid >> 2, aseg = (tid & 3) * 4;
    int bkk = tid >> 4, bnn = (tid & 15) * 4;

    for (int k0 = 0; k0 < UU; k0 += 16) {
        float4 av = *(const float4*)(hin + ab * UU + k0 + aseg);
        float4 wv = *(const float4*)(Wh + (size_t)(k0 + bkk) * G4 + n0 + bnn);
        __syncthreads();
        AsT[aseg + 0][ab] = av.x; AsT[aseg + 1][ab] = av.y;
        AsT[aseg + 2][ab] = av.z; AsT[aseg + 3][ab] = av.w;
        *(float4*)&Bs[bkk][bnn] = wv;
        __syncthreads();
#pragma unroll
        for (int kk = 0; kk < 16; kk++) {
            float4 a = *(float4*)&AsT[kk][ty * 4];
            float4 w = *(float4*)&Bs[kk][tx * 4];
            float aa[4] = {a.x, a.y, a.z, a.w};
            float ww[4] = {w.x, w.y, w.z, w.w};
#pragma unroll
            for (int i = 0; i < 4; i++)
#pragma unroll
                for (int j = 0; j < 4; j++) acc[i][j] += aa[i] * ww[j];
        }
    }

    int u = nb * 16 + tx;                        // global unit index
    float4 bb4 = *(const float4*)(bv + n0 + tx * 4);
#pragma unroll
    for (int i = 0; i < 4; i++) {
        int b = ty * 4 + i;
        float4 pv = *(const float4*)(pre + ((size_t)t * BB + b) * G4 + n0 + tx * 4);
        float gi = acc[i][0] + pv.x + bb4.x;
        float gf = acc[i][1] + pv.y + bb4.y;
        float go = acc[i][2] + pv.z + bb4.z;
        float gg = acc[i][3] + pv.w + bb4.w;
        float ig = 1.f / (1.f + expf(-gi));
        float fg = 1.f / (1.f + expf(-gf));
        float og = 1.f / (1.f + expf(-go));
        float gt = tanhf(gg);
        int su = b * UU + u;
        float c = fg * cst[su] + ig * gt;
        float h = og * tanhf(c);
        cst[su] = c;
        hout[su] = h;
        outp[((size_t)t * BB + b) * ostride + u] = h;
    }
}

// ---------------- span feature gather ----------------------------------------
__global__ void build_hi(const int* __restrict__ sl, const int* __restrict__ sr,
                         const int* __restrict__ ll, const int* __restrict__ lr) {
    int idx = blockIdx.x * blockDim.x + threadIdx.x;   // 64*7*2048 exact
    const int NS = BB * 4 * 2048;
    int b, s, c, le, ri;
    float* dst;
    if (idx < NS) {
        b = idx / (4 * 2048); int r = idx - b * (4 * 2048);
        s = r / 2048; c = r - s * 2048;
        le = sl[b * 4 + s]; ri = sr[b * 4 + s];
        dst = g_hi_s + (size_t)b * 8192 + s * 2048 + c;
    } else {
        int j = idx - NS;
        b = j / (3 * 2048); int r = j - b * (3 * 2048);
        s = r / 2048; c = r - s * 2048;
        le = ll[b * 3 + s]; ri = lr[b * 3 + s];
        dst = g_hi_l + (size_t)b * 6144 + s * 2048 + c;
    }
    float v;
    if (c < 512) {            // fwd1 diff
        v = g_in2[((size_t)ri * BB + b) * 1024 + c] - g_in2[((size_t)(le - 1) * BB + b) * 1024 + c];
    } else if (c < 1024) {    // fwd2 diff
        int u = c - 512;
        v = g_fwd2[((size_t)ri * BB + b) * UU + u] - g_fwd2[((size_t)(le - 1) * BB + b) * UU + u];
    } else if (c < 1536) {    // back1 diff
        int u = c - 1024;
        v = g_in2[((size_t)le * BB + b) * 1024 + 512 + u] - g_in2[((size_t)(ri + 1) * BB + b) * 1024 + 512 + u];
    } else {                  // back2 diff
        int u = c - 1536;
        v = g_back2[((size_t)le * BB + b) * UU + u] - g_back2[((size_t)(ri + 1) * BB + b) * UU + u];
    }
    *dst = v;
}

// ---------------- span hidden GEMM: M=64, split-K into partial planes --------
__global__ void __launch_bounds__(256) span_gemm(
    const float* __restrict__ A, int lda, const float* __restrict__ B,
    float* __restrict__ Cpart) {
    __shared__ float AsT[16][68];
    __shared__ float Bs[16][68];
    int n0 = blockIdx.x * 64;
    int kbase = blockIdx.y * 512;
    int tid = threadIdx.x;
    int tx = tid & 15, ty = tid >> 4;
    float acc[4][4] = {{0}};
    int ab = tid >> 2, aseg = (tid & 3) * 4;
    int bkk = tid >> 4, bnn = (tid & 15) * 4;
    for (int k0 = kbase; k0 < kbase + 512; k0 += 16) {
        float4 av = *(const float4*)(A + (size_t)ab * lda + k0 + aseg);
        float4 wv = *(const float4*)(B + (size_t)(k0 + bkk) * HD + n0 + bnn);
        __syncthreads();
        AsT[aseg + 0][ab] = av.x; AsT[aseg + 1][ab] = av.y;
        AsT[aseg + 2][ab] = av.z; AsT[aseg + 3][ab] = av.w;
        *(float4*)&Bs[bkk][bnn] = wv;
        __syncthreads();
#pragma unroll
        for (int kk = 0; kk < 16; kk++) {
            float4 a = *(float4*)&AsT[kk][ty * 4];
            float4 w = *(float4*)&Bs[kk][tx * 4];
            float aa[4] = {a.x, a.y, a.z, a.w};
            float ww[4] = {w.x, w.y, w.z, w.w};
#pragma unroll
            for (int i = 0; i < 4; i++)
#pragma unroll
                for (int j = 0; j < 4; j++) acc[i][j] += aa[i] * ww[j];
        }
    }
#pragma unroll
    for (int i = 0; i < 4; i++) {
        int b = ty * 4 + i;
        float4 v = {acc[i][0], acc[i][1], acc[i][2], acc[i][3]};
        *(float4*)(Cpart + ((size_t)blockIdx.y * BB + b) * HD + n0 + tx * 4) = v;
    }
}

__global__ void reduce_relu(const float* __restrict__ part, int nch,
                            const float* __restrict__ bias, float* __restrict__ outh) {
    int idx = blockIdx.x * blockDim.x + threadIdx.x;   // 64*1024
    int n = idx & (HD - 1);
    float s = bias[n];
    for (int ch = 0; ch < nch; ch++) s += part[(size_t)ch * BB * HD + idx];
    outh[idx] = fmaxf(s, 0.f);
}

// ---------------- output heads ------------------------------------------------
__global__ void out_heads(const float* __restrict__ soW, const float* __restrict__ sob,
                          const float* __restrict__ loW, const float* __restrict__ lob,
                          float* __restrict__ out) {
    __shared__ float s1[HD], s2[HD];
    int b = blockIdx.x, tid = threadIdx.x;
    for (int i = tid; i < HD; i += blockDim.x) {
        s1[i] = g_hs[b * HD + i];
        s2[i] = g_hl[b * HD + i];
    }
    __syncthreads();
    if (tid < 2) {
        float s = sob[tid];
        for (int k = 0; k < HD; k++) s += s1[k] * soW[k * 2 + tid];
        out[b * 2 + tid] = s;
    } else if (tid < 34) {
        int j = tid - 2;
        float s = lob[j];
        for (int k = 0; k < HD; k++) s += s2[k] * loW[k * 32 + j];
        out[128 + b * 32 + j] = s;
    }
}

// ---------------- host driver --------------------------------------------------
static float* sym(const void* symbol) {
    void* p = nullptr;
    cudaGetSymbolAddress(&p, symbol);
    return (float*)p;
}

extern "C" void kernel_launch(void* const* d_in, const int* in_sizes, int n_in,
                              void* d_out, int out_size) {
    const float* word_emb = (const float*)d_in[0];
    const float* tag_emb  = (const float*)d_in[1];
    const float* l1f_W = (const float*)d_in[2];
    const float* l1f_b = (const float*)d_in[3];
    const float* l1f_c0 = (const float*)d_in[4];
    const float* l1b_W = (const float*)d_in[5];
    const float* l1b_b = (const float*)d_in[6];
    const float* l1b_c0 = (const float*)d_in[7];
    const float* l2f_W = (const float*)d_in[8];
    const float* l2f_b = (const float*)d_in[9];
    const float* l2f_c0 = (const float*)d_in[10];
    const float* l2b_W = (const float*)d_in[11];
    const float* l2b_b = (const float*)d_in[12];
    const float* l2b_c0 = (const float*)d_in[13];
    const float* sh_W = (const float*)d_in[14];
    const float* sh_b = (const float*)d_in[15];
    const float* so_W = (const float*)d_in[16];
    const float* so_b = (const float*)d_in[17];
    const float* lh_W = (const float*)d_in[18];
    const float* lh_b = (const float*)d_in[19];
    const float* lo_W = (const float*)d_in[20];
    const float* lo_b = (const float*)d_in[21];
    const int* word_inds = (const int*)d_in[22];
    const int* tag_inds  = (const int*)d_in[23];
    const int* s_lefts  = (const int*)d_in[24];
    const int* s_rights = (const int*)d_in[25];
    const int* l_lefts  = (const int*)d_in[26];
    const int* l_rights = (const int*)d_in[27];
    float* out = (float*)d_out;

    float* p_sent  = sym(g_sent);
    float* p_preF  = sym(g_preF);
    float* p_preB  = sym(g_preB);
    float* p_in2   = sym(g_in2);
    float* p_fwd2  = sym(g_fwd2);
    float* p_back2 = sym(g_back2);
    float* p_Wx1f = sym(g_Wx1f); float* p_Wx1b = sym(g_Wx1b);
    float* p_Wh1f = sym(g_Wh1f); float* p_Wh1b = sym(g_Wh1b);
    float* p_Wx2f = sym(g_Wx2f); float* p_Wx2b = sym(g_Wx2b);
    float* p_Wh2f = sym(g_Wh2f); float* p_Wh2b = sym(g_Wh2b);
    float* p_bv1f = sym(g_bv1f); float* p_bv1b = sym(g_bv1b);
    float* p_bv2f = sym(g_bv2f); float* p_bv2b = sym(g_bv2b);
    float* p_hFa = sym(g_hFa); float* p_hFb = sym(g_hFb);
    float* p_hBa = sym(g_hBa); float* p_hBb = sym(g_hBb);
    float* p_hi_s = sym(g_hi_s); float* p_hi_l = sym(g_hi_l);
    float* p_part_s = sym(g_part_s); float* p_part_l = sym(g_part_l);
    float* p_hs = sym(g_hs); float* p_hl = sym(g_hl);

    // 1) pack weights (gate-interleaved columns)
    pack_lstm<<<2048, 256>>>(l1f_W, l1f_b, p_Wx1f, p_Wh1f, p_bv1f, SENT_D);
    pack_lstm<<<2048, 256>>>(l1b_W, l1b_b, p_Wx1b, p_Wh1b, p_bv1b, SENT_D);
    pack_lstm<<<4096, 256>>>(l2f_W, l2f_b, p_Wx2f, p_Wh2f, p_bv2f, 1024);
    pack_lstm<<<4096, 256>>>(l2b_W, l2b_b, p_Wx2b, p_Wh2b, p_bv2b, 1024);

    // 2) embeddings
    embed_kernel<<<(T_LEN * BB * SENT_D) / 256, 256>>>(word_emb, tag_emb, word_inds, tag_inds);

    // 3) layer-1 input projections: pre = sent @ Wx  (16384 x 320 x 2048)
    dim3 gpre(G4 / 128, (T_LEN * BB) / 128);
    sgemm_128x128<<<gpre, 256>>>(p_sent, p_Wx1f, p_preF, SENT_D, SENT_D, G4, G4);
    sgemm_128x128<<<gpre, 256>>>(p_sent, p_Wx1b, p_preB, SENT_D, SENT_D, G4, G4);

    // 4) layer-1 recurrence (fwd+back fused), writes into g_in2 slices
    init_states<<<(BB * UU) / 256, 256>>>(l1f_c0, l1b_c0);
    for (int s = 0; s < T_LEN; s++) {
        const float* hinF = (s & 1) ? p_hFb : p_hFa;
        float* houtF      = (s & 1) ? p_hFa : p_hFb;
        const float* hinB = (s & 1) ? p_hBb : p_hBa;
        float* houtB      = (s & 1) ? p_hBa : p_hBb;
        lstm_step<<<64, 256>>>(p_preF, p_preB, p_Wh1f, p_Wh1b, p_bv1f, p_bv1b,
                               hinF, houtF, hinB, houtB,
                               p_in2, p_in2 + 512, 1024, s, T_LEN - 1 - s);
    }

    // 5) layer-2 input projections: pre = in2 @ Wx2 (16384 x 1024 x 2048)
    sgemm_128x128<<<gpre, 256>>>(p_in2, p_Wx2f, p_preF, 1024, 1024, G4, G4);
    sgemm_128x128<<<gpre, 256>>>(p_in2, p_Wx2b, p_preB, 1024, 1024, G4, G4);

    // 6) layer-2 recurrence
    init_states<<<(BB * UU) / 256, 256>>>(l2f_c0, l2b_c0);
    for (int s = 0; s < T_LEN; s++) {
        const float* hinF = (s & 1) ? p_hFb : p_hFa;
        float* houtF      = (s & 1) ? p_hFa : p_hFb;
        const float* hinB = (s & 1) ? p_hBb : p_hBa;
        float* houtB      = (s & 1) ? p_hBa : p_hBb;
        lstm_step<<<64, 256>>>(p_preF, p_preB, p_Wh2f, p_Wh2b, p_bv2f, p_bv2b,
                               hinF, houtF, hinB, houtB,
                               p_fwd2, p_back2, UU, s, T_LEN - 1 - s);
    }

    // 7) span features
    build_hi<<<(BB * 7 * 2048) / 256, 256>>>(s_lefts, s_rights, l_lefts, l_rights);

    // 8) span hidden layers (split-K partials, deterministic reduce + relu)
    span_gemm<<<dim3(HD / 64, 16), 256>>>(p_hi_s, 8192, sh_W, p_part_s);
    span_gemm<<<dim3(HD / 64, 12), 256>>>(p_hi_l, 6144, lh_W, p_part_l);
    reduce_relu<<<(BB * HD) / 256, 256>>>(p_part_s, 16, sh_b, p_hs);
    reduce_relu<<<(BB * HD) / 256, 256>>>(p_part_l, 12, lh_b, p_hl);

    // 9) output heads -> d_out: struct (64x2) then label (64x32)
    out_heads<<<BB, 128>>>(so_W, so_b, lo_W, lo_b, out);
}

// round 3
// speedup vs baseline: 1.4635x; 1.4635x over previous
#include <cuda_runtime.h>
#include <math.h>

#define T_LEN 256
#define BB 64
#define SENT_D 320
#define UU 512
#define G4 2048
#define HD 1024

// ---------------- scratch (device globals; no allocs allowed) ----------------
__device__ float g_sent[T_LEN * BB * SENT_D];
__device__ float g_preF[(size_t)T_LEN * BB * G4];
__device__ float g_preB[(size_t)T_LEN * BB * G4];
__device__ float g_in2[(size_t)T_LEN * BB * 1024];   // [t][b][0:512]=fwd1, [512:1024]=back1
__device__ float g_fwd2[(size_t)T_LEN * BB * UU];
__device__ float g_back2[(size_t)T_LEN * BB * UU];

__device__ float g_Wx1f[SENT_D * G4], g_Wx1b[SENT_D * G4];
__device__ float g_Wh1f[UU * G4],     g_Wh1b[UU * G4];
__device__ float g_Wx2f[1024 * G4],   g_Wx2b[1024 * G4];
__device__ float g_Wh2f[UU * G4],     g_Wh2b[UU * G4];
__device__ float g_bv1f[G4], g_bv1b[G4], g_bv2f[G4], g_bv2b[G4];

__device__ float g_hFa[BB * UU], g_hFb[BB * UU];
__device__ float g_hBa[BB * UU], g_hBb[BB * UU];
__device__ float g_cF[BB * UU],  g_cB[BB * UU];

__device__ float g_hi_s[BB * 8192];
__device__ float g_hi_l[BB * 6144];
__device__ float g_part_s[16 * BB * HD];
__device__ float g_part_l[12 * BB * HD];
__device__ float g_hs[BB * HD], g_hl[BB * HD];

// ---------------- weight packing: column n = u*4 + k (gate-interleaved) ------
__global__ void pack_lstm(const float* __restrict__ W, const float* __restrict__ b,
                          float* __restrict__ Wx, float* __restrict__ Wh,
                          float* __restrict__ bv, int din) {
    int total = 4 * (din + UU) * UU;
    int stride = gridDim.x * blockDim.x;
    for (int idx = blockIdx.x * blockDim.x + threadIdx.x; idx < total; idx += stride) {
        int k = idx / ((din + UU) * UU);
        int rem = idx - k * ((din + UU) * UU);
        int d = rem / UU;
        int u = rem - d * UU;
        float v = W[idx];
        int n = u * 4 + k;
        if (d < din) Wx[(size_t)d * G4 + n] = v;
        else         Wh[(size_t)(d - din) * G4 + n] = v;
    }
    for (int i = blockIdx.x * blockDim.x + threadIdx.x; i < G4; i += stride) {
        int k = i & 3, u = i >> 2;
        bv[i] = b[k * UU + u];
    }
}

// ---------------- embedding gather + concat ----------------------------------
__global__ void embed_kernel(const float* __restrict__ we, const float* __restrict__ te,
                             const int* __restrict__ wi, const int* __restrict__ ti) {
    int idx = blockIdx.x * blockDim.x + threadIdx.x;   // grid sized exactly
    int tb = idx / SENT_D;
    int j = idx - tb * SENT_D;
    float v;
    if (j < 256) v = we[(size_t)wi[tb] * 256 + j];
    else         v = te[(size_t)ti[tb] * 64 + (j - 256)];
    g_sent[idx] = v;
}

// ---------------- LSTM state init --------------------------------------------
__global__ void init_states(const float* __restrict__ c0f, const float* __restrict__ c0b) {
    int idx = blockIdx.x * blockDim.x + threadIdx.x;   // B*U = 32768
    int u = idx & (UU - 1);
    float cf = c0f[u], cb = c0b[u];
    g_cF[idx] = cf;  g_hFa[idx] = tanhf(cf);
    g_cB[idx] = cb;  g_hBa[idx] = tanhf(cb);
}

// ---------------- big SGEMM: C = A@B, 128x128 tiles, fp32 --------------------
__global__ void __launch_bounds__(256) sgemm_128x128(
    const float* __restrict__ A, const float* __restrict__ B, float* __restrict__ C,
    int K, int lda, int ldb, int ldc) {
    __shared__ float As[16][132];   // As[kk][m]
    __shared__ float Bs[16][132];   // Bs[kk][n]
    int m0 = blockIdx.y * 128, n0 = blockIdx.x * 128;
    int tid = threadIdx.x;
    int tx = tid & 15, ty = tid >> 4;
    float acc[8][8];
#pragma unroll
    for (int i = 0; i < 8; i++)
#pragma unroll
        for (int j = 0; j < 8; j++) acc[i][j] = 0.f;

    int ar = tid >> 2, ac = (tid & 3) * 4;
    int bk = tid >> 5, bn = (tid & 31) * 4;

    for (int k0 = 0; k0 < K; k0 += 16) {
        float4 a0 = *(const float4*)(A + (size_t)(m0 + ar) * lda + k0 + ac);
        float4 a1 = *(const float4*)(A + (size_t)(m0 + ar + 64) * lda + k0 + ac);
        float4 b0 = *(const float4*)(B + (size_t)(k0 + bk) * ldb + n0 + bn);
        float4 b1 = *(const float4*)(B + (size_t)(k0 + bk + 8) * ldb + n0 + bn);
        __syncthreads();
        As[ac + 0][ar] = a0.x; As[ac + 1][ar] = a0.y; As[ac + 2][ar] = a0.z; As[ac + 3][ar] = a0.w;
        As[ac + 0][ar + 64] = a1.x; As[ac + 1][ar + 64] = a1.y; As[ac + 2][ar + 64] = a1.z; As[ac + 3][ar + 64] = a1.w;
        *(float4*)&Bs[bk][bn] = b0;
        *(float4*)&Bs[bk + 8][bn] = b1;
        __syncthreads();
#pragma unroll
        for (int kk = 0; kk < 16; kk++) {
            float4 av0 = *(float4*)&As[kk][ty * 8];
            float4 av1 = *(float4*)&As[kk][ty * 8 + 4];
            float4 bv0 = *(float4*)&Bs[kk][tx * 8];
            float4 bv1 = *(float4*)&Bs[kk][tx * 8 + 4];
            float a[8] = {av0.x, av0.y, av0.z, av0.w, av1.x, av1.y, av1.z, av1.w};
            float bb[8] = {bv0.x, bv0.y, bv0.z, bv0.w, bv1.x, bv1.y, bv1.z, bv1.w};
#pragma unroll
            for (int i = 0; i < 8; i++)
#pragma unroll
                for (int j = 0; j < 8; j++) acc[i][j] += a[i] * bb[j];
        }
    }
#pragma unroll
    for (int i = 0; i < 8; i++) {
        float4 v0 = {acc[i][0], acc[i][1], acc[i][2], acc[i][3]};
        float4 v1 = {acc[i][4], acc[i][5], acc[i][6], acc[i][7]};
        float* cp = C + (size_t)(m0 + ty * 8 + i) * ldc + n0 + tx * 8;
        *(float4*)cp = v0;
        *(float4*)(cp + 4) = v1;
    }
}

// ---------------- one recurrent step, both directions fused ------------------
// grid = 128 CTAs x 128 threads: blk>>6 = dir, blk&63 = 32-wide gate tile
// (8 complete units). Output tile 64(b) x 32(gate), 4x4 per thread.
__global__ void __launch_bounds__(128) lstm_step(
    const float* __restrict__ preF, const float* __restrict__ preB,
    const float* __restrict__ WhF,  const float* __restrict__ WhB,
    const float* __restrict__ bvF,  const float* __restrict__ bvB,
    const float* __restrict__ hinF, float* __restrict__ houtF,
    const float* __restrict__ hinB, float* __restrict__ houtB,
    float* __restrict__ outF, float* __restrict__ outB,
    int ostride, int tF, int tB) {
    __shared__ float AsT[16][68];   // AsT[kk][b]
    __shared__ float Bs[16][36];    // Bs[kk][n]
    int blk = blockIdx.x;
    int dir = blk >> 6;
    int nb = blk & 63;
    int n0 = nb * 32;

    const float* pre = dir ? preB : preF;
    const float* Wh  = dir ? WhB : WhF;
    const float* bv  = dir ? bvB : bvF;
    const float* hin = dir ? hinB : hinF;
    float* hout = dir ? houtB : houtF;
    float* cst  = dir ? g_cB : g_cF;
    float* outp = dir ? outB : outF;
    int t = dir ? tB : tF;

    int tid = threadIdx.x;
    int tx = tid & 7;      // 8 col-groups of 4 gates
    int ty = tid >> 3;     // 16 row-groups of 4 batch rows
    float acc[4][4] = {{0}};

    int ar = tid >> 1, ac = (tid & 1) * 8;      // A: 64 rows x 16 k, 2 float4/thread
    int bkk = tid >> 3, bnn = (tid & 7) * 4;    // B: 16 k x 32 n, 1 float4/thread

    for (int k0 = 0; k0 < UU; k0 += 16) {
        float4 a0 = *(const float4*)(hin + ar * UU + k0 + ac);
        float4 a1 = *(const float4*)(hin + ar * UU + k0 + ac + 4);
        float4 wv = *(const float4*)(Wh + (size_t)(k0 + bkk) * G4 + n0 + bnn);
        __syncthreads();
        AsT[ac + 0][ar] = a0.x; AsT[ac + 1][ar] = a0.y;
        AsT[ac + 2][ar] = a0.z; AsT[ac + 3][ar] = a0.w;
        AsT[ac + 4][ar] = a1.x; AsT[ac + 5][ar] = a1.y;
        AsT[ac + 6][ar] = a1.z; AsT[ac + 7][ar] = a1.w;
        *(float4*)&Bs[bkk][bnn] = wv;
        __syncthreads();
#pragma unroll
        for (int kk = 0; kk < 16; kk++) {
            float4 a = *(float4*)&AsT[kk][ty * 4];
            float4 w = *(float4*)&Bs[kk][tx * 4];
            float aa[4] = {a.x, a.y, a.z, a.w};
            float ww[4] = {w.x, w.y, w.z, w.w};
#pragma unroll
            for (int i = 0; i < 4; i++)
#pragma unroll
                for (int j = 0; j < 4; j++) acc[i][j] += aa[i] * ww[j];
        }
    }

    int u = nb * 8 + tx;                        // global unit index
    float4 bb4 = *(const float4*)(bv + n0 + tx * 4);
#pragma unroll
    for (int i = 0; i < 4; i++) {
        int b = ty * 4 + i;
        float4 pv = *(const float4*)(pre + ((size_t)t * BB + b) * G4 + n0 + tx * 4);
        float gi = acc[i][0] + pv.x + bb4.x;
        float gf = acc[i][1] + pv.y + bb4.y;
        float go = acc[i][2] + pv.z + bb4.z;
        float gg = acc[i][3] + pv.w + bb4.w;
        float ig = 1.f / (1.f + expf(-gi));
        float fg = 1.f / (1.f + expf(-gf));
        float og = 1.f / (1.f + expf(-go));
        float gt = tanhf(gg);
        int su = b * UU + u;
        float c = fg * cst[su] + ig * gt;
        float h = og * tanhf(c);
        cst[su] = c;
        hout[su] = h;
        outp[((size_t)t * BB + b) * ostride + u] = h;
    }
}

// ---------------- span feature gather ----------------------------------------
__global__ void build_hi(const int* __restrict__ sl, const int* __restrict__ sr,
                         const int* __restrict__ ll, const int* __restrict__ lr) {
    int idx = blockIdx.x * blockDim.x + threadIdx.x;   // 64*7*2048 exact
    const int NS = BB * 4 * 2048;
    int b, s, c, le, ri;
    float* dst;
    if (idx < NS) {
        b = idx / (4 * 2048); int r = idx - b * (4 * 2048);
        s = r / 2048; c = r - s * 2048;
        le = sl[b * 4 + s]; ri = sr[b * 4 + s];
        dst = g_hi_s + (size_t)b * 8192 + s * 2048 + c;
    } else {
        int j = idx - NS;
        b = j / (3 * 2048); int r = j - b * (3 * 2048);
        s = r / 2048; c = r - s * 2048;
        le = ll[b * 3 + s]; ri = lr[b * 3 + s];
        dst = g_hi_l + (size_t)b * 6144 + s * 2048 + c;
    }
    float v;
    if (c < 512) {            // fwd1 diff
        v = g_in2[((size_t)ri * BB + b) * 1024 + c] - g_in2[((size_t)(le - 1) * BB + b) * 1024 + c];
    } else if (c < 1024) {    // fwd2 diff
        int u = c - 512;
        v = g_fwd2[((size_t)ri * BB + b) * UU + u] - g_fwd2[((size_t)(le - 1) * BB + b) * UU + u];
    } else if (c < 1536) {    // back1 diff
        int u = c - 1024;
        v = g_in2[((size_t)le * BB + b) * 1024 + 512 + u] - g_in2[((size_t)(ri + 1) * BB + b) * 1024 + 512 + u];
    } else {                  // back2 diff
        int u = c - 1536;
        v = g_back2[((size_t)le * BB + b) * UU + u] - g_back2[((size_t)(ri + 1) * BB + b) * UU + u];
    }
    *dst = v;
}

// ---------------- span hidden GEMM: M=64, split-K into partial planes --------
__global__ void __launch_bounds__(256) span_gemm(
    const float* __restrict__ A, int lda, const float* __restrict__ B,
    float* __restrict__ Cpart) {
    __shared__ float AsT[16][68];
    __shared__ float Bs[16][68];
    int n0 = blockIdx.x * 64;
    int kbase = blockIdx.y * 512;
    int tid = threadIdx.x;
    int tx = tid & 15, ty = tid >> 4;
    float acc[4][4] = {{0}};
    int ab = tid >> 2, aseg = (tid & 3) * 4;
    int bkk = tid >> 4, bnn = (tid & 15) * 4;
    for (int k0 = kbase; k0 < kbase + 512; k0 += 16) {
        float4 av = *(const float4*)(A + (size_t)ab * lda + k0 + aseg);
        float4 wv = *(const float4*)(B + (size_t)(k0 + bkk) * HD + n0 + bnn);
        __syncthreads();
        AsT[aseg + 0][ab] = av.x; AsT[aseg + 1][ab] = av.y;
        AsT[aseg + 2][ab] = av.z; AsT[aseg + 3][ab] = av.w;
        *(float4*)&Bs[bkk][bnn] = wv;
        __syncthreads();
#pragma unroll
        for (int kk = 0; kk < 16; kk++) {
            float4 a = *(float4*)&AsT[kk][ty * 4];
            float4 w = *(float4*)&Bs[kk][tx * 4];
            float aa[4] = {a.x, a.y, a.z, a.w};
            float ww[4] = {w.x, w.y, w.z, w.w};
#pragma unroll
            for (int i = 0; i < 4; i++)
#pragma unroll
                for (int j = 0; j < 4; j++) acc[i][j] += aa[i] * ww[j];
        }
    }
#pragma unroll
    for (int i = 0; i < 4; i++) {
        int b = ty * 4 + i;
        float4 v = {acc[i][0], acc[i][1], acc[i][2], acc[i][3]};
        *(float4*)(Cpart + ((size_t)blockIdx.y * BB + b) * HD + n0 + tx * 4) = v;
    }
}

__global__ void reduce_relu(const float* __restrict__ part, int nch,
                            const float* __restrict__ bias, float* __restrict__ outh) {
    int idx = blockIdx.x * blockDim.x + threadIdx.x;   // 64*1024
    int n = idx & (HD - 1);
    float s = bias[n];
    for (int ch = 0; ch < nch; ch++) s += part[(size_t)ch * BB * HD + idx];
    outh[idx] = fmaxf(s, 0.f);
}

// ---------------- output heads ------------------------------------------------
__global__ void out_heads(const float* __restrict__ soW, const float* __restrict__ sob,
                          const float* __restrict__ loW, const float* __restrict__ lob,
                          float* __restrict__ out) {
    __shared__ float s1[HD], s2[HD];
    int b = blockIdx.x, tid = threadIdx.x;
    for (int i = tid; i < HD; i += blockDim.x) {
        s1[i] = g_hs[b * HD + i];
        s2[i] = g_hl[b * HD + i];
    }
    __syncthreads();
    if (tid < 2) {
        float s = sob[tid];
        for (int k = 0; k < HD; k++) s += s1[k] * soW[k * 2 + tid];
        out[b * 2 + tid] = s;
    } else if (tid < 34) {
        int j = tid - 2;
        float s = lob[j];
        for (int k = 0; k < HD; k++) s += s2[k] * loW[k * 32 + j];
        out[128 + b * 32 + j] = s;
    }
}

// ---------------- host driver --------------------------------------------------
static float* sym(const void* symbol) {
    void* p = nullptr;
    cudaGetSymbolAddress(&p, symbol);
    return (float*)p;
}

extern "C" void kernel_launch(void* const* d_in, const int* in_sizes, int n_in,
                              void* d_out, int out_size) {
    const float* word_emb = (const float*)d_in[0];
    const float* tag_emb  = (const float*)d_in[1];
    const float* l1f_W = (const float*)d_in[2];
    const float* l1f_b = (const float*)d_in[3];
    const float* l1f_c0 = (const float*)d_in[4];
    const float* l1b_W = (const float*)d_in[5];
    const float* l1b_b = (const float*)d_in[6];
    const float* l1b_c0 = (const float*)d_in[7];
    const float* l2f_W = (const float*)d_in[8];
    const float* l2f_b = (const float*)d_in[9];
    const float* l2f_c0 = (const float*)d_in[10];
    const float* l2b_W = (const float*)d_in[11];
    const float* l2b_b = (const float*)d_in[12];
    const float* l2b_c0 = (const float*)d_in[13];
    const float* sh_W = (const float*)d_in[14];
    const float* sh_b = (const float*)d_in[15];
    const float* so_W = (const float*)d_in[16];
    const float* so_b = (const float*)d_in[17];
    const float* lh_W = (const float*)d_in[18];
    const float* lh_b = (const float*)d_in[19];
    const float* lo_W = (const float*)d_in[20];
    const float* lo_b = (const float*)d_in[21];
    const int* word_inds = (const int*)d_in[22];
    const int* tag_inds  = (const int*)d_in[23];
    const int* s_lefts  = (const int*)d_in[24];
    const int* s_rights = (const int*)d_in[25];
    const int* l_lefts  = (const int*)d_in[26];
    const int* l_rights = (const int*)d_in[27];
    float* out = (float*)d_out;

    float* p_sent  = sym(g_sent);
    float* p_preF  = sym(g_preF);
    float* p_preB  = sym(g_preB);
    float* p_in2   = sym(g_in2);
    float* p_fwd2  = sym(g_fwd2);
    float* p_back2 = sym(g_back2);
    float* p_Wx1f = sym(g_Wx1f); float* p_Wx1b = sym(g_Wx1b);
    float* p_Wh1f = sym(g_Wh1f); float* p_Wh1b = sym(g_Wh1b);
    float* p_Wx2f = sym(g_Wx2f); float* p_Wx2b = sym(g_Wx2b);
    float* p_Wh2f = sym(g_Wh2f); float* p_Wh2b = sym(g_Wh2b);
    float* p_bv1f = sym(g_bv1f); float* p_bv1b = sym(g_bv1b);
    float* p_bv2f = sym(g_bv2f); float* p_bv2b = sym(g_bv2b);
    float* p_hFa = sym(g_hFa); float* p_hFb = sym(g_hFb);
    float* p_hBa = sym(g_hBa); float* p_hBb = sym(g_hBb);
    float* p_hi_s = sym(g_hi_s); float* p_hi_l = sym(g_hi_l);
    float* p_part_s = sym(g_part_s); float* p_part_l = sym(g_part_l);
    float* p_hs = sym(g_hs); float* p_hl = sym(g_hl);

    // 1) pack weights (gate-interleaved columns)
    pack_lstm<<<2048, 256>>>(l1f_W, l1f_b, p_Wx1f, p_Wh1f, p_bv1f, SENT_D);
    pack_lstm<<<2048, 256>>>(l1b_W, l1b_b, p_Wx1b, p_Wh1b, p_bv1b, SENT_D);
    pack_lstm<<<4096, 256>>>(l2f_W, l2f_b, p_Wx2f, p_Wh2f, p_bv2f, 1024);
    pack_lstm<<<4096, 256>>>(l2b_W, l2b_b, p_Wx2b, p_Wh2b, p_bv2b, 1024);

    // 2) embeddings
    embed_kernel<<<(T_LEN * BB * SENT_D) / 256, 256>>>(word_emb, tag_emb, word_inds, tag_inds);

    // 3) layer-1 input projections: pre = sent @ Wx  (16384 x 320 x 2048)
    dim3 gpre(G4 / 128, (T_LEN * BB) / 128);
    sgemm_128x128<<<gpre, 256>>>(p_sent, p_Wx1f, p_preF, SENT_D, SENT_D, G4, G4);
    sgemm_128x128<<<gpre, 256>>>(p_sent, p_Wx1b, p_preB, SENT_D, SENT_D, G4, G4);

    // 4) layer-1 recurrence (fwd+back fused), writes into g_in2 slices
    init_states<<<(BB * UU) / 256, 256>>>(l1f_c0, l1b_c0);
    for (int s = 0; s < T_LEN; s++) {
        const float* hinF = (s & 1) ? p_hFb : p_hFa;
        float* houtF      = (s & 1) ? p_hFa : p_hFb;
        const float* hinB = (s & 1) ? p_hBb : p_hBa;
        float* houtB      = (s & 1) ? p_hBa : p_hBb;
        lstm_step<<<128, 128>>>(p_preF, p_preB, p_Wh1f, p_Wh1b, p_bv1f, p_bv1b,
                                hinF, houtF, hinB, houtB,
                                p_in2, p_in2 + 512, 1024, s, T_LEN - 1 - s);
    }

    // 5) layer-2 input projections: pre = in2 @ Wx2 (16384 x 1024 x 2048)
    sgemm_128x128<<<gpre, 256>>>(p_in2, p_Wx2f, p_preF, 1024, 1024, G4, G4);
    sgemm_128x128<<<gpre, 256>>>(p_in2, p_Wx2b, p_preB, 1024, 1024, G4, G4);

    // 6) layer-2 recurrence
    init_states<<<(BB * UU) / 256, 256>>>(l2f_c0, l2b_c0);
    for (int s = 0; s < T_LEN; s++) {
        const float* hinF = (s & 1) ? p_hFb : p_hFa;
        float* houtF      = (s & 1) ? p_hFa : p_hFb;
        const float* hinB = (s & 1) ? p_hBb : p_hBa;
        float* houtB      = (s & 1) ? p_hBa : p_hBb;
        lstm_step<<<128, 128>>>(p_preF, p_preB, p_Wh2f, p_Wh2b, p_bv2f, p_bv2b,
                                hinF, houtF, hinB, houtB,
                                p_fwd2, p_back2, UU, s, T_LEN - 1 - s);
    }

    // 7) span features
    build_hi<<<(BB * 7 * 2048) / 256, 256>>>(s_lefts, s_rights, l_lefts, l_rights);

    // 8) span hidden layers (split-K partials, deterministic reduce + relu)
    span_gemm<<<dim3(HD / 64, 16), 256>>>(p_hi_s, 8192, sh_W, p_part_s);
    span_gemm<<<dim3(HD / 64, 12), 256>>>(p_hi_l, 6144, lh_W, p_part_l);
    reduce_relu<<<(BB * HD) / 256, 256>>>(p_part_s, 16, sh_b, p_hs);
    reduce_relu<<<(BB * HD) / 256, 256>>>(p_part_l, 12, lh_b, p_hl);

    // 9) output heads -> d_out: struct (64x2) then label (64x32)
    out_heads<<<BB, 128>>>(so_W, so_b, lo_W, lo_b, out);
}

// round 4
// speedup vs baseline: 1.5067x; 1.0295x over previous
#include <cuda_runtime.h>
#include <math.h>

#define T_LEN 256
#define BB 64
#define SENT_D 320
#define UU 512
#define G4 2048
#define HD 1024

// ---------------- packed f32x2 helpers (Blackwell FFMA2) ---------------------
__device__ __forceinline__ void fma2(unsigned long long& d,
                                     unsigned long long a, unsigned long long b) {
    asm("fma.rn.f32x2 %0, %1, %2, %0;" : "+l"(d) : "l"(a), "l"(b));
}
__device__ __forceinline__ unsigned long long dup2(float x) {
    unsigned long long r;
    asm("mov.b64 %0, {%1, %1};" : "=l"(r) : "f"(x));
    return r;
}
__device__ __forceinline__ float2 unpack2(unsigned long long v) {
    float2 r;
    asm("mov.b64 {%0, %1}, %2;" : "=f"(r.x), "=f"(r.y) : "l"(v));
    return r;
}

// ---------------- scratch (device globals; no allocs allowed) ----------------
__device__ float g_sent[T_LEN * BB * SENT_D];
__device__ float g_preF[(size_t)T_LEN * BB * G4];
__device__ float g_preB[(size_t)T_LEN * BB * G4];
__device__ float g_in2[(size_t)T_LEN * BB * 1024];   // [t][b][0:512]=fwd1, [512:1024]=back1
__device__ float g_fwd2[(size_t)T_LEN * BB * UU];
__device__ float g_back2[(size_t)T_LEN * BB * UU];

__device__ float g_Wx1f[SENT_D * G4], g_Wx1b[SENT_D * G4];
__device__ float g_Wh1f[UU * G4],     g_Wh1b[UU * G4];
__device__ float g_Wx2f[1024 * G4],   g_Wx2b[1024 * G4];
__device__ float g_Wh2f[UU * G4],     g_Wh2b[UU * G4];
__device__ float g_bv1f[G4], g_bv1b[G4], g_bv2f[G4], g_bv2b[G4];

__device__ float g_hFa[BB * UU], g_hFb[BB * UU];
__device__ float g_hBa[BB * UU], g_hBb[BB * UU];
__device__ float g_cF[BB * UU],  g_cB[BB * UU];

__device__ float g_hi_s[BB * 8192];
__device__ float g_hi_l[BB * 6144];
__device__ float g_part_s[16 * BB * HD];
__device__ float g_part_l[12 * BB * HD];
__device__ float g_hs[BB * HD], g_hl[BB * HD];

// ---------------- weight packing: column n = u*4 + k (gate-interleaved) ------
__global__ void pack_lstm(const float* __restrict__ W, const float* __restrict__ b,
                          float* __restrict__ Wx, float* __restrict__ Wh,
                          float* __restrict__ bv, int din) {
    int total = 4 * (din + UU) * UU;
    int stride = gridDim.x * blockDim.x;
    for (int idx = blockIdx.x * blockDim.x + threadIdx.x; idx < total; idx += stride) {
        int k = idx / ((din + UU) * UU);
        int rem = idx - k * ((din + UU) * UU);
        int d = rem / UU;
        int u = rem - d * UU;
        float v = W[idx];
        int n = u * 4 + k;
        if (d < din) Wx[(size_t)d * G4 + n] = v;
        else         Wh[(size_t)(d - din) * G4 + n] = v;
    }
    for (int i = blockIdx.x * blockDim.x + threadIdx.x; i < G4; i += stride) {
        int k = i & 3, u = i >> 2;
        bv[i] = b[k * UU + u];
    }
}

// ---------------- embedding gather + concat ----------------------------------
__global__ void embed_kernel(const float* __restrict__ we, const float* __restrict__ te,
                             const int* __restrict__ wi, const int* __restrict__ ti) {
    int idx = blockIdx.x * blockDim.x + threadIdx.x;
    int tb = idx / SENT_D;
    int j = idx - tb * SENT_D;
    float v;
    if (j < 256) v = we[(size_t)wi[tb] * 256 + j];
    else         v = te[(size_t)ti[tb] * 64 + (j - 256)];
    g_sent[idx] = v;
}

// ---------------- LSTM state init --------------------------------------------
__global__ void init_states(const float* __restrict__ c0f, const float* __restrict__ c0b) {
    int idx = blockIdx.x * blockDim.x + threadIdx.x;   // B*U = 32768
    int u = idx & (UU - 1);
    float cf = c0f[u], cb = c0b[u];
    g_cF[idx] = cf;  g_hFa[idx] = tanhf(cf);
    g_cB[idx] = cb;  g_hBa[idx] = tanhf(cb);
}

// ---------------- big SGEMM: C = A@B, 128x128 tiles, FFMA2 -------------------
__global__ void __launch_bounds__(256) sgemm_128x128(
    const float* __restrict__ A, const float* __restrict__ B, float* __restrict__ C,
    int K, int lda, int ldb, int ldc) {
    __shared__ float As[16][132];   // As[kk][m]  (row-pairs load free via LDS.64)
    __shared__ float Bs[16][132];   // Bs[kk][n]
    int m0 = blockIdx.y * 128, n0 = blockIdx.x * 128;
    int tid = threadIdx.x;
    int tx = tid & 15, ty = tid >> 4;
    unsigned long long acc[4][8];   // [m-pair][n] ; pair = rows (ty*8+2p, ty*8+2p+1)
#pragma unroll
    for (int p = 0; p < 4; p++)
#pragma unroll
        for (int j = 0; j < 8; j++) acc[p][j] = 0ULL;

    int ar = tid >> 2, ac = (tid & 3) * 4;
    int bk = tid >> 5, bn = (tid & 31) * 4;

    for (int k0 = 0; k0 < K; k0 += 16) {
        float4 a0 = *(const float4*)(A + (size_t)(m0 + ar) * lda + k0 + ac);
        float4 a1 = *(const float4*)(A + (size_t)(m0 + ar + 64) * lda + k0 + ac);
        float4 b0 = *(const float4*)(B + (size_t)(k0 + bk) * ldb + n0 + bn);
        float4 b1 = *(const float4*)(B + (size_t)(k0 + bk + 8) * ldb + n0 + bn);
        __syncthreads();
        As[ac + 0][ar] = a0.x; As[ac + 1][ar] = a0.y; As[ac + 2][ar] = a0.z; As[ac + 3][ar] = a0.w;
        As[ac + 0][ar + 64] = a1.x; As[ac + 1][ar + 64] = a1.y; As[ac + 2][ar + 64] = a1.z; As[ac + 3][ar + 64] = a1.w;
        *(float4*)&Bs[bk][bn] = b0;
        *(float4*)&Bs[bk + 8][bn] = b1;
        __syncthreads();
#pragma unroll
        for (int kk = 0; kk < 16; kk++) {
            unsigned long long ap[4];
#pragma unroll
            for (int p = 0; p < 4; p++)
                ap[p] = *(const unsigned long long*)&As[kk][ty * 8 + 2 * p];
            float4 bv0 = *(float4*)&Bs[kk][tx * 8];
            float4 bv1 = *(float4*)&Bs[kk][tx * 8 + 4];
            unsigned long long bd[8] = {dup2(bv0.x), dup2(bv0.y), dup2(bv0.z), dup2(bv0.w),
                                        dup2(bv1.x), dup2(bv1.y), dup2(bv1.z), dup2(bv1.w)};
#pragma unroll
            for (int p = 0; p < 4; p++)
#pragma unroll
                for (int j = 0; j < 8; j++) fma2(acc[p][j], ap[p], bd[j]);
        }
    }
#pragma unroll
    for (int p = 0; p < 4; p++) {
        float v0[8], v1[8];
#pragma unroll
        for (int j = 0; j < 8; j++) {
            float2 t = unpack2(acc[p][j]);
            v0[j] = t.x; v1[j] = t.y;
        }
        float* c0 = C + (size_t)(m0 + ty * 8 + 2 * p) * ldc + n0 + tx * 8;
        float* c1 = c0 + ldc;
        *(float4*)c0 = make_float4(v0[0], v0[1], v0[2], v0[3]);
        *(float4*)(c0 + 4) = make_float4(v0[4], v0[5], v0[6], v0[7]);
        *(float4*)c1 = make_float4(v1[0], v1[1], v1[2], v1[3]);
        *(float4*)(c1 + 4) = make_float4(v1[4], v1[5], v1[6], v1[7]);
    }
}

// ---------------- one recurrent step, both directions fused (FFMA2) ----------
// grid = 128 CTAs x 128 threads: blk>>6 = dir, blk&63 = 32-wide gate tile
// (8 complete units). Output tile 64(b) x 32(gate), per-thread 4x4 as 2 b-pairs.
__global__ void __launch_bounds__(128) lstm_step(
    const float* __restrict__ preF, const float* __restrict__ preB,
    const float* __restrict__ WhF,  const float* __restrict__ WhB,
    const float* __restrict__ bvF,  const float* __restrict__ bvB,
    const float* __restrict__ hinF, float* __restrict__ houtF,
    const float* __restrict__ hinB, float* __restrict__ houtB,
    float* __restrict__ outF, float* __restrict__ outB,
    int ostride, int tF, int tB) {
    __shared__ float AsT[16][68];   // AsT[kk][b]
    __shared__ float Bs[16][36];    // Bs[kk][n]
    int blk = blockIdx.x;
    int dir = blk >> 6;
    int nb = blk & 63;
    int n0 = nb * 32;

    const float* pre = dir ? preB : preF;
    const float* Wh  = dir ? WhB : WhF;
    const float* bv  = dir ? bvB : bvF;
    const float* hin = dir ? hinB : hinF;
    float* hout = dir ? houtB : houtF;
    float* cst  = dir ? g_cB : g_cF;
    float* outp = dir ? outB : outF;
    int t = dir ? tB : tF;

    int tid = threadIdx.x;
    int tx = tid & 7;      // 8 col-groups of 4 gates
    int ty = tid >> 3;     // 16 row-groups of 4 batch rows
    unsigned long long acc[2][4];  // [b-pair][gate]
#pragma unroll
    for (int p = 0; p < 2; p++)
#pragma unroll
        for (int j = 0; j < 4; j++) acc[p][j] = 0ULL;

    int ar = tid >> 1, ac = (tid & 1) * 8;      // A: 64 rows x 16 k, 2 float4/thread
    int bkk = tid >> 3, bnn = (tid & 7) * 4;    // B: 16 k x 32 n, 1 float4/thread

    for (int k0 = 0; k0 < UU; k0 += 16) {
        float4 a0 = *(const float4*)(hin + ar * UU + k0 + ac);
        float4 a1 = *(const float4*)(hin + ar * UU + k0 + ac + 4);
        float4 wv = *(const float4*)(Wh + (size_t)(k0 + bkk) * G4 + n0 + bnn);
        __syncthreads();
        AsT[ac + 0][ar] = a0.x; AsT[ac + 1][ar] = a0.y;
        AsT[ac + 2][ar] = a0.z; AsT[ac + 3][ar] = a0.w;
        AsT[ac + 4][ar] = a1.x; AsT[ac + 5][ar] = a1.y;
        AsT[ac + 6][ar] = a1.z; AsT[ac + 7][ar] = a1.w;
        *(float4*)&Bs[bkk][bnn] = wv;
        __syncthreads();
#pragma unroll
        for (int kk = 0; kk < 16; kk++) {
            unsigned long long a01 = *(const unsigned long long*)&AsT[kk][ty * 4];
            unsigned long long a23 = *(const unsigned long long*)&AsT[kk][ty * 4 + 2];
            float4 w = *(float4*)&Bs[kk][tx * 4];
            unsigned long long w0 = dup2(w.x), w1 = dup2(w.y),
                               w2 = dup2(w.z), w3 = dup2(w.w);
            fma2(acc[0][0], a01, w0); fma2(acc[0][1], a01, w1);
            fma2(acc[0][2], a01, w2); fma2(acc[0][3], a01, w3);
            fma2(acc[1][0], a23, w0); fma2(acc[1][1], a23, w1);
            fma2(acc[1][2], a23, w2); fma2(acc[1][3], a23, w3);
        }
    }

    int u = nb * 8 + tx;                        // global unit index
    float4 bb4 = *(const float4*)(bv + n0 + tx * 4);
#pragma unroll
    for (int i = 0; i < 4; i++) {
        int p = i >> 1, s = i & 1;
        float g0, g1, g2, g3;
        {
            float2 t0 = unpack2(acc[p][0]);
            float2 t1 = unpack2(acc[p][1]);
            float2 t2 = unpack2(acc[p][2]);
            float2 t3 = unpack2(acc[p][3]);
            g0 = s ? t0.y : t0.x;
            g1 = s ? t1.y : t1.x;
            g2 = s ? t2.y : t2.x;
            g3 = s ? t3.y : t3.x;
        }
        int b = ty * 4 + i;
        float4 pv = *(const float4*)(pre + ((size_t)t * BB + b) * G4 + n0 + tx * 4);
        float gi = g0 + pv.x + bb4.x;
        float gf = g1 + pv.y + bb4.y;
        float go = g2 + pv.z + bb4.z;
        float gg = g3 + pv.w + bb4.w;
        float ig = 1.f / (1.f + expf(-gi));
        float fg = 1.f / (1.f + expf(-gf));
        float og = 1.f / (1.f + expf(-go));
        float gt = tanhf(gg);
        int su = b * UU + u;
        float c = fg * cst[su] + ig * gt;
        float h = og * tanhf(c);
        cst[su] = c;
        hout[su] = h;
        outp[((size_t)t * BB + b) * ostride + u] = h;
    }
}

// ---------------- span feature gather ----------------------------------------
__global__ void build_hi(const int* __restrict__ sl, const int* __restrict__ sr,
                         const int* __restrict__ ll, const int* __restrict__ lr) {
    int idx = blockIdx.x * blockDim.x + threadIdx.x;   // 64*7*2048 exact
    const int NS = BB * 4 * 2048;
    int b, s, c, le, ri;
    float* dst;
    if (idx < NS) {
        b = idx / (4 * 2048); int r = idx - b * (4 * 2048);
        s = r / 2048; c = r - s * 2048;
        le = sl[b * 4 + s]; ri = sr[b * 4 + s];
        dst = g_hi_s + (size_t)b * 8192 + s * 2048 + c;
    } else {
        int j = idx - NS;
        b = j / (3 * 2048); int r = j - b * (3 * 2048);
        s = r / 2048; c = r - s * 2048;
        le = ll[b * 3 + s]; ri = lr[b * 3 + s];
        dst = g_hi_l + (size_t)b * 6144 + s * 2048 + c;
    }
    float v;
    if (c < 512) {
        v = g_in2[((size_t)ri * BB + b) * 1024 + c] - g_in2[((size_t)(le - 1) * BB + b) * 1024 + c];
    } else if (c < 1024) {
        int u = c - 512;
        v = g_fwd2[((size_t)ri * BB + b) * UU + u] - g_fwd2[((size_t)(le - 1) * BB + b) * UU + u];
    } else if (c < 1536) {
        int u = c - 1024;
        v = g_in2[((size_t)le * BB + b) * 1024 + 512 + u] - g_in2[((size_t)(ri + 1) * BB + b) * 1024 + 512 + u];
    } else {
        int u = c - 1536;
        v = g_back2[((size_t)le * BB + b) * UU + u] - g_back2[((size_t)(ri + 1) * BB + b) * UU + u];
    }
    *dst = v;
}

// ---------------- span hidden GEMM: M=64, split-K into partial planes --------
__global__ void __launch_bounds__(256) span_gemm(
    const float* __restrict__ A, int lda, const float* __restrict__ B,
    float* __restrict__ Cpart) {
    __shared__ float AsT[16][68];
    __shared__ float Bs[16][68];
    int n0 = blockIdx.x * 64;
    int kbase = blockIdx.y * 512;
    int tid = threadIdx.x;
    int tx = tid & 15, ty = tid >> 4;
    float acc[4][4] = {{0}};
    int ab = tid >> 2, aseg = (tid & 3) * 4;
    int bkk = tid >> 4, bnn = (tid & 15) * 4;
    for (int k0 = kbase; k0 < kbase + 512; k0 += 16) {
        float4 av = *(const float4*)(A + (size_t)ab * lda + k0 + aseg);
        float4 wv = *(const float4*)(B + (size_t)(k0 + bkk) * HD + n0 + bnn);
        __syncthreads();
        AsT[aseg + 0][ab] = av.x; AsT[aseg + 1][ab] = av.y;
        AsT[aseg + 2][ab] = av.z; AsT[aseg + 3][ab] = av.w;
        *(float4*)&Bs[bkk][bnn] = wv;
        __syncthreads();
#pragma unroll
        for (int kk = 0; kk < 16; kk++) {
            float4 a = *(float4*)&AsT[kk][ty * 4];
            float4 w = *(float4*)&Bs[kk][tx * 4];
            float aa[4] = {a.x, a.y, a.z, a.w};
            float ww[4] = {w.x, w.y, w.z, w.w};
#pragma unroll
            for (int i = 0; i < 4; i++)
#pragma unroll
                for (int j = 0; j < 4; j++) acc[i][j] += aa[i] * ww[j];
        }
    }
#pragma unroll
    for (int i = 0; i < 4; i++) {
        int b = ty * 4 + i;
        float4 v = {acc[i][0], acc[i][1], acc[i][2], acc[i][3]};
        *(float4*)(Cpart + ((size_t)blockIdx.y * BB + b) * HD + n0 + tx * 4) = v;
    }
}

__global__ void reduce_relu(const float* __restrict__ part, int nch,
                            const float* __restrict__ bias, float* __restrict__ outh) {
    int idx = blockIdx.x * blockDim.x + threadIdx.x;   // 64*1024
    int n = idx & (HD - 1);
    float s = bias[n];
    for (int ch = 0; ch < nch; ch++) s += part[(size_t)ch * BB * HD + idx];
    outh[idx] = fmaxf(s, 0.f);
}

// ---------------- output heads ------------------------------------------------
__global__ void out_heads(const float* __restrict__ soW, const float* __restrict__ sob,
                          const float* __restrict__ loW, const float* __restrict__ lob,
                          float* __restrict__ out) {
    __shared__ float s1[HD], s2[HD];
    int b = blockIdx.x, tid = threadIdx.x;
    for (int i = tid; i < HD; i += blockDim.x) {
        s1[i] = g_hs[b * HD + i];
        s2[i] = g_hl[b * HD + i];
    }
    __syncthreads();
    if (tid < 2) {
        float s = sob[tid];
        for (int k = 0; k < HD; k++) s += s1[k] * soW[k * 2 + tid];
        out[b * 2 + tid] = s;
    } else if (tid < 34) {
        int j = tid - 2;
        float s = lob[j];
        for (int k = 0; k < HD; k++) s += s2[k] * loW[k * 32 + j];
        out[128 + b * 32 + j] = s;
    }
}

// ---------------- host driver --------------------------------------------------
static float* sym(const void* symbol) {
    void* p = nullptr;
    cudaGetSymbolAddress(&p, symbol);
    return (float*)p;
}

extern "C" void kernel_launch(void* const* d_in, const int* in_sizes, int n_in,
                              void* d_out, int out_size) {
    const float* word_emb = (const float*)d_in[0];
    const float* tag_emb  = (const float*)d_in[1];
    const float* l1f_W = (const float*)d_in[2];
    const float* l1f_b = (const float*)d_in[3];
    const float* l1f_c0 = (const float*)d_in[4];
    const float* l1b_W = (const float*)d_in[5];
    const float* l1b_b = (const float*)d_in[6];
    const float* l1b_c0 = (const float*)d_in[7];
    const float* l2f_W = (const float*)d_in[8];
    const float* l2f_b = (const float*)d_in[9];
    const float* l2f_c0 = (const float*)d_in[10];
    const float* l2b_W = (const float*)d_in[11];
    const float* l2b_b = (const float*)d_in[12];
    const float* l2b_c0 = (const float*)d_in[13];
    const float* sh_W = (const float*)d_in[14];
    const float* sh_b = (const float*)d_in[15];
    const float* so_W = (const float*)d_in[16];
    const float* so_b = (const float*)d_in[17];
    const float* lh_W = (const float*)d_in[18];
    const float* lh_b = (const float*)d_in[19];
    const float* lo_W = (const float*)d_in[20];
    const float* lo_b = (const float*)d_in[21];
    const int* word_inds = (const int*)d_in[22];
    const int* tag_inds  = (const int*)d_in[23];
    const int* s_lefts  = (const int*)d_in[24];
    const int* s_rights = (const int*)d_in[25];
    const int* l_lefts  = (const int*)d_in[26];
    const int* l_rights = (const int*)d_in[27];
    float* out = (float*)d_out;

    float* p_sent  = sym(g_sent);
    float* p_preF  = sym(g_preF);
    float* p_preB  = sym(g_preB);
    float* p_in2   = sym(g_in2);
    float* p_fwd2  = sym(g_fwd2);
    float* p_back2 = sym(g_back2);
    float* p_Wx1f = sym(g_Wx1f); float* p_Wx1b = sym(g_Wx1b);
    float* p_Wh1f = sym(g_Wh1f); float* p_Wh1b = sym(g_Wh1b);
    float* p_Wx2f = sym(g_Wx2f); float* p_Wx2b = sym(g_Wx2b);
    float* p_Wh2f = sym(g_Wh2f); float* p_Wh2b = sym(g_Wh2b);
    float* p_bv1f = sym(g_bv1f); float* p_bv1b = sym(g_bv1b);
    float* p_bv2f = sym(g_bv2f); float* p_bv2b = sym(g_bv2b);
    float* p_hFa = sym(g_hFa); float* p_hFb = sym(g_hFb);
    float* p_hBa = sym(g_hBa); float* p_hBb = sym(g_hBb);
    float* p_hi_s = sym(g_hi_s); float* p_hi_l = sym(g_hi_l);
    float* p_part_s = sym(g_part_s); float* p_part_l = sym(g_part_l);
    float* p_hs = sym(g_hs); float* p_hl = sym(g_hl);

    // 1) pack weights (gate-interleaved columns)
    pack_lstm<<<2048, 256>>>(l1f_W, l1f_b, p_Wx1f, p_Wh1f, p_bv1f, SENT_D);
    pack_lstm<<<2048, 256>>>(l1b_W, l1b_b, p_Wx1b, p_Wh1b, p_bv1b, SENT_D);
    pack_lstm<<<4096, 256>>>(l2f_W, l2f_b, p_Wx2f, p_Wh2f, p_bv2f, 1024);
    pack_lstm<<<4096, 256>>>(l2b_W, l2b_b, p_Wx2b, p_Wh2b, p_bv2b, 1024);

    // 2) embeddings
    embed_kernel<<<(T_LEN * BB * SENT_D) / 256, 256>>>(word_emb, tag_emb, word_inds, tag_inds);

    // 3) layer-1 input projections: pre = sent @ Wx  (16384 x 320 x 2048)
    dim3 gpre(G4 / 128, (T_LEN * BB) / 128);
    sgemm_128x128<<<gpre, 256>>>(p_sent, p_Wx1f, p_preF, SENT_D, SENT_D, G4, G4);
    sgemm_128x128<<<gpre, 256>>>(p_sent, p_Wx1b, p_preB, SENT_D, SENT_D, G4, G4);

    // 4) layer-1 recurrence (fwd+back fused), writes into g_in2 slices
    init_states<<<(BB * UU) / 256, 256>>>(l1f_c0, l1b_c0);
    for (int s = 0; s < T_LEN; s++) {
        const float* hinF = (s & 1) ? p_hFb : p_hFa;
        float* houtF      = (s & 1) ? p_hFa : p_hFb;
        const float* hinB = (s & 1) ? p_hBb : p_hBa;
        float* houtB      = (s & 1) ? p_hBa : p_hBb;
        lstm_step<<<128, 128>>>(p_preF, p_preB, p_Wh1f, p_Wh1b, p_bv1f, p_bv1b,
                                hinF, houtF, hinB, houtB,
                                p_in2, p_in2 + 512, 1024, s, T_LEN - 1 - s);
    }

    // 5) layer-2 input projections: pre = in2 @ Wx2 (16384 x 1024 x 2048)
    sgemm_128x128<<<gpre, 256>>>(p_in2, p_Wx2f, p_preF, 1024, 1024, G4, G4);
    sgemm_128x128<<<gpre, 256>>>(p_in2, p_Wx2b, p_preB, 1024, 1024, G4, G4);

    // 6) layer-2 recurrence
    init_states<<<(BB * UU) / 256, 256>>>(l2f_c0, l2b_c0);
    for (int s = 0; s < T_LEN; s++) {
        const float* hinF = (s & 1) ? p_hFb : p_hFa;
        float* houtF      = (s & 1) ? p_hFa : p_hFb;
        const float* hinB = (s & 1) ? p_hBb : p_hBa;
        float* houtB      = (s & 1) ? p_hBa : p_hBb;
        lstm_step<<<128, 128>>>(p_preF, p_preB, p_Wh2f, p_Wh2b, p_bv2f, p_bv2b,
                                hinF, houtF, hinB, houtB,
                                p_fwd2, p_back2, UU, s, T_LEN - 1 - s);
    }

    // 7) span features
    build_hi<<<(BB * 7 * 2048) / 256, 256>>>(s_lefts, s_rights, l_lefts, l_rights);

    // 8) span hidden layers (split-K partials, deterministic reduce + relu)
    span_gemm<<<dim3(HD / 64, 16), 256>>>(p_hi_s, 8192, sh_W, p_part_s);
    span_gemm<<<dim3(HD / 64, 12), 256>>>(p_hi_l, 6144, lh_W, p_part_l);
    reduce_relu<<<(BB * HD) / 256, 256>>>(p_part_s, 16, sh_b, p_hs);
    reduce_relu<<<(BB * HD) / 256, 256>>>(p_part_l, 12, lh_b, p_hl);

    // 9) output heads -> d_out: struct (64x2) then label (64x32)
    out_heads<<<BB, 128>>>(so_W, so_b, lo_W, lo_b, out);
}